// round 14
// baseline (speedup 1.0000x reference)
#include <cuda_runtime.h>
#include <cuda_fp16.h>
#include <cstdint>

// Problem shape
#define B_DIM 4096
#define T_DIM 256
#define TD 16384             // T*D stride per batch row
#define NBI 262144           // B*64 flattened (b,i)
#define JCS 65               // zgp chunk stride in float4 (bank spread)

// K powers: g_Kp[(k-1)*4096 + i*64 + j] = (K^k)[i][j], k=1..12
__device__ float g_Kp[12 * 4096];
// Split B fragments, plane-pair-major:
//  g_zfA[q*NBI + bi] = uint2(h01, l01)  -> planes {2q, 2q+1}
//  g_zfB[q*NBI + bi] = uint2(h89, l89)  -> planes {2q+8, 2q+9}
__device__ uint2 g_zfA[4 * NBI];
__device__ uint2 g_zfB[4 * NBI];
// A fragments (t^k hi/lo): [mf*32 + lane]
__device__ uint4 g_tfH[16 * 32];
__device__ uint4 g_tfL[16 * 32];

__constant__ float c_coef[13] = {
    1.0f, 1.0f, 0.5f, 1.6666666666667e-1f, 4.1666666666667e-2f,
    8.3333333333333e-3f, 1.3888888888889e-3f, 1.9841269841270e-4f,
    2.4801587301587e-5f, 2.7557319223986e-6f, 2.7557319223986e-7f,
    2.5052108385442e-8f, 2.0876756987868e-9f};

// ---------------- helpers ----------------
__device__ __forceinline__ void split2h(float x, float y, uint32_t& H, uint32_t& L) {
    __half hx = __float2half_rn(x);
    __half hy = __float2half_rn(y);
    __half lx = __float2half_rn(x - __half2float(hx));
    __half ly = __float2half_rn(y - __half2float(hy));
    __half2 hh = __halves2half2(hx, hy);
    __half2 ll = __halves2half2(lx, ly);
    H = *(uint32_t*)&hh;
    L = *(uint32_t*)&ll;
}
__device__ __forceinline__ void mma16816h(float* c, const uint4& a, uint32_t b0, uint32_t b1) {
    asm volatile(
        "mma.sync.aligned.m16n8k16.row.col.f32.f16.f16.f32 "
        "{%0,%1,%2,%3}, {%4,%5,%6,%7}, {%8,%9}, {%0,%1,%2,%3};"
        : "+f"(c[0]), "+f"(c[1]), "+f"(c[2]), "+f"(c[3])
        : "r"(a.x), "r"(a.y), "r"(a.z), "r"(a.w), "r"(b0), "r"(b1));
}
__device__ __forceinline__ void stg_cs2(float* p, float x, float y) {
    asm volatile("st.global.cs.v2.f32 [%0], {%1, %2};"
                 :: "l"(p), "f"(x), "f"(y) : "memory");
}

// ---------------- kpow (+ t-fragments) — R13-measured, unchanged ----------------
extern "C" __global__ void __launch_bounds__(64)
kpow_kernel(const float* __restrict__ Kmat, const float* __restrict__ time) {
    if (blockIdx.x >= 64) {
        int e = (blockIdx.x - 64) * 64 + threadIdx.x;   // 0..511 = mf*32 + lane
        int lane = e & 31;
        int mf = e >> 5;
        int r0 = mf * 16 + (lane >> 2);
        int r1 = r0 + 8;
        int k0 = (lane & 3) * 2;

        float t0 = time[r0], t1 = time[r1];
        float p0[16], p1[16];
        p0[0] = 1.f; p1[0] = 1.f;
#pragma unroll
        for (int k = 1; k < 13; k++) { p0[k] = p0[k - 1] * t0; p1[k] = p1[k - 1] * t1; }
#pragma unroll
        for (int k = 13; k < 16; k++) { p0[k] = 0.f; p1[k] = 0.f; }

        uint4 H, L;
        split2h(p0[k0], p0[k0 + 1], H.x, L.x);
        split2h(p1[k0], p1[k0 + 1], H.y, L.y);
        split2h(p0[k0 + 8], p0[k0 + 9], H.z, L.z);
        split2h(p1[k0 + 8], p1[k0 + 9], H.w, L.w);
        g_tfH[e] = H;
        g_tfL[e] = L;
        return;
    }

    __shared__ float vbuf[2][64];
    const int i = threadIdx.x;
    const int c = blockIdx.x;

    float kr[64];
    {
        const float4* kp = (const float4*)(Kmat + i * 64);
#pragma unroll
        for (int q = 0; q < 16; q++) {
            float4 v = kp[q];
            kr[q * 4 + 0] = v.x; kr[q * 4 + 1] = v.y;
            kr[q * 4 + 2] = v.z; kr[q * 4 + 3] = v.w;
        }
    }

    float v0 = Kmat[i * 64 + c];
    vbuf[0][i] = v0;
    g_Kp[i * 64 + c] = v0;
    __syncthreads();

    int cur = 0;
#pragma unroll
    for (int k = 2; k <= 12; k++) {
        const float4* vq = (const float4*)vbuf[cur];
        float s0 = 0.f, s1 = 0.f, s2 = 0.f, s3 = 0.f;
#pragma unroll
        for (int jq = 0; jq < 16; jq++) {
            float4 vv = vq[jq];
            s0 = fmaf(kr[jq * 4 + 0], vv.x, s0);
            s1 = fmaf(kr[jq * 4 + 1], vv.y, s1);
            s2 = fmaf(kr[jq * 4 + 2], vv.z, s2);
            s3 = fmaf(kr[jq * 4 + 3], vv.w, s3);
        }
        float s = (s0 + s1) + (s2 + s3);
        vbuf[cur ^ 1][i] = s;
        g_Kp[(k - 1) * 4096 + i * 64 + c] = s;
        cur ^= 1;
        __syncthreads();
    }
}

// ---------------- zgp: plane-pair GEMM, conflict-free chunked tiles (R13) ------
extern "C" __global__ void __launch_bounds__(256)
zgp_kernel(const float* __restrict__ inputs) {
    __shared__ float4 xs[16 * JCS];
    __shared__ float4 ks[16 * JCS];
    const int tid = threadIdx.x;
    const int ty = tid >> 4, tx = tid & 15;
    const int b0 = blockIdx.x * 64;
    const int p = blockIdx.y;
    uint2* dst = (p < 4 ? g_zfA : g_zfB) + (size_t)(p & 3) * NBI;

    if (p == 7) {
        // planes 14,15: identically zero (contiguous uint4 fill)
#pragma unroll
        for (int r = 0; r < 4; r++) {
            int bi = (b0 + ty * 4 + r) * 64 + tx * 4;
            *(uint4*)&dst[bi]     = make_uint4(0, 0, 0, 0);
            *(uint4*)&dst[bi + 2] = make_uint4(0, 0, 0, 0);
        }
        return;
    }

    // load x0 tile: xs[(j>>2)*JCS + r] = x0[b0+r][j..j+3]
#pragma unroll
    for (int l = 0; l < 4; l++) {
        int idx4 = l * 256 + tid;
        int el = idx4 * 4;
        int r = el >> 6, j = el & 63;
        xs[(j >> 2) * JCS + r] = *(const float4*)(inputs + (size_t)(b0 + r) * TD + j);
    }
    __syncthreads();

    float accP[2][4][4];
#pragma unroll
    for (int pl = 0; pl < 2; pl++)
#pragma unroll
        for (int r = 0; r < 4; r++)
#pragma unroll
            for (int c = 0; c < 4; c++) accP[pl][r][c] = 0.f;

#pragma unroll
    for (int pl = 0; pl < 2; pl++) {
        const int kk = 2 * p + pl;
        if (kk == 0) {
#pragma unroll
            for (int r = 0; r < 4; r++)
#pragma unroll
                for (int c = 0; c < 4; c++) {
                    int j = tx + 16 * c;
                    accP[0][r][c] = ((const float*)&xs[(j >> 2) * JCS + ty * 4 + r])[j & 3];
                }
        } else if (kk <= 12) {
            const float* kp = g_Kp + (kk - 1) * 4096;
#pragma unroll
            for (int l = 0; l < 4; l++) {
                int idx4 = l * 256 + tid;
                int el = idx4 * 4;
                int r = el >> 6, j = el & 63;
                ks[(j >> 2) * JCS + r] = *(const float4*)(kp + el);
            }
            __syncthreads();
#pragma unroll 4
            for (int jc = 0; jc < 16; jc++) {
                float4 a4[4], b4[4];
#pragma unroll
                for (int r = 0; r < 4; r++) a4[r] = xs[jc * JCS + ty * 4 + r];
#pragma unroll
                for (int c = 0; c < 4; c++) b4[c] = ks[jc * JCS + tx + 16 * c];
#pragma unroll
                for (int r = 0; r < 4; r++)
#pragma unroll
                    for (int c = 0; c < 4; c++) {
                        float s = accP[pl][r][c];
                        s = fmaf(a4[r].x, b4[c].x, s);
                        s = fmaf(a4[r].y, b4[c].y, s);
                        s = fmaf(a4[r].z, b4[c].z, s);
                        s = fmaf(a4[r].w, b4[c].w, s);
                        accP[pl][r][c] = s;
                    }
            }
            __syncthreads();   // before next plane's ks load
        }
        // kk == 13: stays zero
    }

    const float ck0 = (2 * p     <= 12) ? c_coef[2 * p]     : 0.f;
    const float ck1 = (2 * p + 1 <= 12) ? c_coef[2 * p + 1] : 0.f;

    // store: element (b0+ty*4+r, tx+16c) -> dst[bi]; per-warp 2x128B runs per STG
#pragma unroll
    for (int r = 0; r < 4; r++) {
        int bir = (b0 + ty * 4 + r) * 64 + tx;
#pragma unroll
        for (int c = 0; c < 4; c++) {
            uint32_t h, l;
            split2h(accP[0][r][c] * ck0, accP[1][r][c] * ck1, h, l);
            dst[bir + 16 * c] = make_uint2(h, l);
        }
    }
}

// ---------------- eval: direct .cs stores, low-reg (4 nf/warp) ----------------
// grid (1024, 2) x 256 thr. Warp W2 = bx*8+wid: b = W2>>1, i-half h = W2&1
// (4 nf = 32 i). blockIdx.y selects 8 of 16 t-fragment rows. 3-term fp16 split.
// Each 4-lane group's float2 stores cover a full 32B sector; .cs = evict-first.
extern "C" __global__ void __launch_bounds__(256)
eval_kernel(float* __restrict__ out) {
    const int tid = threadIdx.x;
    const int wid = tid >> 5, lane = tid & 31;
    const int W2 = blockIdx.x * 8 + wid;
    const int b = W2 >> 1;
    const int h = W2 & 1;
    const int mf0 = blockIdx.y * 8;

    const int q = lane & 3;
    const int nl = lane >> 2;
    const size_t zbase = (size_t)q * NBI + b * 64 + h * 32 + nl;
    uint2 zA[4], zB[4];
#pragma unroll
    for (int nf = 0; nf < 4; nf++) {
        zA[nf] = g_zfA[zbase + nf * 8];
        zB[nf] = g_zfB[zbase + nf * 8];
    }

    const int r = lane >> 2;
    const int cb = (lane & 3) * 2;
    float* obase = out + (size_t)b * TD + h * 32 + cb;

#pragma unroll 1
    for (int mi = 0; mi < 8; mi++) {
        const int mf = mf0 + mi;
        uint4 ah = g_tfH[mf * 32 + lane];
        uint4 al = g_tfL[mf * 32 + lane];

        float acc[4][4];
#pragma unroll
        for (int nf = 0; nf < 4; nf++)
#pragma unroll
            for (int q2 = 0; q2 < 4; q2++) acc[nf][q2] = 0.f;

#pragma unroll
        for (int nf = 0; nf < 4; nf++) {
            mma16816h(acc[nf], ah, zA[nf].x, zB[nf].x);   // hi * hi
            mma16816h(acc[nf], ah, zA[nf].y, zB[nf].y);   // hi * lo
            mma16816h(acc[nf], al, zA[nf].x, zB[nf].x);   // lo * hi
        }

        // direct streaming stores: rows t = mf*16 + r (+8)
        float* op  = obase + (size_t)(mf * 16 + r) * 64;
        float* op8 = op + 8 * 64;
#pragma unroll
        for (int nf = 0; nf < 4; nf++) {
            stg_cs2(op  + nf * 8, acc[nf][0], acc[nf][1]);
            stg_cs2(op8 + nf * 8, acc[nf][2], acc[nf][3]);
        }
    }
}

// ---------------- launch ----------------
extern "C" void kernel_launch(void* const* d_in, const int* in_sizes, int n_in,
                              void* d_out, int out_size) {
    const float* inputs = (const float*)d_in[0];
    const float* time   = (const float*)d_in[1];
    const float* kern   = (const float*)d_in[2];
    float* out = (float*)d_out;

    kpow_kernel<<<72, 64>>>(kern, time);
    zgp_kernel<<<dim3(64, 8), 256>>>(inputs);
    eval_kernel<<<dim3(1024, 2), 256>>>(out);
}

// round 15
// speedup vs baseline: 1.4791x; 1.4791x over previous
#include <cuda_runtime.h>
#include <cuda_fp16.h>
#include <cstdint>

// Problem shape
#define B_DIM 4096
#define T_DIM 256
#define TD 16384             // T*D stride per batch row
#define NBI 262144           // B*64 flattened (b,i)
#define JCS 65               // zgp ks chunk stride in float4 (bank spread)
#define JXS 33               // zgp xs chunk stride in float4 (32-row tile)

// K powers: g_Kp[(k-1)*4096 + i*64 + j] = (K^k)[i][j], k=1..12
__device__ float g_Kp[12 * 4096];
// Split B fragments, plane-pair-major:
//  g_zfA[q*NBI + bi] = uint2(h01, l01)  -> planes {2q, 2q+1}
//  g_zfB[q*NBI + bi] = uint2(h89, l89)  -> planes {2q+8, 2q+9}
__device__ uint2 g_zfA[4 * NBI];
__device__ uint2 g_zfB[4 * NBI];
// A fragments (t^k hi/lo): [mf*32 + lane]
__device__ uint4 g_tfH[16 * 32];
__device__ uint4 g_tfL[16 * 32];

__constant__ float c_coef[13] = {
    1.0f, 1.0f, 0.5f, 1.6666666666667e-1f, 4.1666666666667e-2f,
    8.3333333333333e-3f, 1.3888888888889e-3f, 1.9841269841270e-4f,
    2.4801587301587e-5f, 2.7557319223986e-6f, 2.7557319223986e-7f,
    2.5052108385442e-8f, 2.0876756987868e-9f};

// ---------------- helpers ----------------
__device__ __forceinline__ void split2h(float x, float y, uint32_t& H, uint32_t& L) {
    __half hx = __float2half_rn(x);
    __half hy = __float2half_rn(y);
    __half lx = __float2half_rn(x - __half2float(hx));
    __half ly = __float2half_rn(y - __half2float(hy));
    __half2 hh = __halves2half2(hx, hy);
    __half2 ll = __halves2half2(lx, ly);
    H = *(uint32_t*)&hh;
    L = *(uint32_t*)&ll;
}
__device__ __forceinline__ void mma16816h(float* c, const uint4& a, uint32_t b0, uint32_t b1) {
    asm volatile(
        "mma.sync.aligned.m16n8k16.row.col.f32.f16.f16.f32 "
        "{%0,%1,%2,%3}, {%4,%5,%6,%7}, {%8,%9}, {%0,%1,%2,%3};"
        : "+f"(c[0]), "+f"(c[1]), "+f"(c[2]), "+f"(c[3])
        : "r"(a.x), "r"(a.y), "r"(a.z), "r"(a.w), "r"(b0), "r"(b1));
}
__device__ __forceinline__ void stg_cs4(float* p, float4 v) {
    asm volatile("st.global.cs.v4.f32 [%0], {%1, %2, %3, %4};"
                 :: "l"(p), "f"(v.x), "f"(v.y), "f"(v.z), "f"(v.w) : "memory");
}

// ---------------- kpow (+ t-fragments) — R13-measured, unchanged ----------------
extern "C" __global__ void __launch_bounds__(64)
kpow_kernel(const float* __restrict__ Kmat, const float* __restrict__ time) {
    if (blockIdx.x >= 64) {
        int e = (blockIdx.x - 64) * 64 + threadIdx.x;   // 0..511 = mf*32 + lane
        int lane = e & 31;
        int mf = e >> 5;
        int r0 = mf * 16 + (lane >> 2);
        int r1 = r0 + 8;
        int k0 = (lane & 3) * 2;

        float t0 = time[r0], t1 = time[r1];
        float p0[16], p1[16];
        p0[0] = 1.f; p1[0] = 1.f;
#pragma unroll
        for (int k = 1; k < 13; k++) { p0[k] = p0[k - 1] * t0; p1[k] = p1[k - 1] * t1; }
#pragma unroll
        for (int k = 13; k < 16; k++) { p0[k] = 0.f; p1[k] = 0.f; }

        uint4 H, L;
        split2h(p0[k0], p0[k0 + 1], H.x, L.x);
        split2h(p1[k0], p1[k0 + 1], H.y, L.y);
        split2h(p0[k0 + 8], p0[k0 + 9], H.z, L.z);
        split2h(p1[k0 + 8], p1[k0 + 9], H.w, L.w);
        g_tfH[e] = H;
        g_tfL[e] = L;
        return;
    }

    __shared__ float vbuf[2][64];
    const int i = threadIdx.x;
    const int c = blockIdx.x;

    float kr[64];
    {
        const float4* kp = (const float4*)(Kmat + i * 64);
#pragma unroll
        for (int q = 0; q < 16; q++) {
            float4 v = kp[q];
            kr[q * 4 + 0] = v.x; kr[q * 4 + 1] = v.y;
            kr[q * 4 + 2] = v.z; kr[q * 4 + 3] = v.w;
        }
    }

    float v0 = Kmat[i * 64 + c];
    vbuf[0][i] = v0;
    g_Kp[i * 64 + c] = v0;
    __syncthreads();

    int cur = 0;
#pragma unroll
    for (int k = 2; k <= 12; k++) {
        const float4* vq = (const float4*)vbuf[cur];
        float s0 = 0.f, s1 = 0.f, s2 = 0.f, s3 = 0.f;
#pragma unroll
        for (int jq = 0; jq < 16; jq++) {
            float4 vv = vq[jq];
            s0 = fmaf(kr[jq * 4 + 0], vv.x, s0);
            s1 = fmaf(kr[jq * 4 + 1], vv.y, s1);
            s2 = fmaf(kr[jq * 4 + 2], vv.z, s2);
            s3 = fmaf(kr[jq * 4 + 3], vv.w, s3);
        }
        float s = (s0 + s1) + (s2 + s3);
        vbuf[cur ^ 1][i] = s;
        g_Kp[(k - 1) * 4096 + i * 64 + c] = s;
        cur ^= 1;
        __syncthreads();
    }
}

// ---------------- zgp: plane-pair GEMM, 32-row b-blocks (load-balanced) --------
// grid (128 b-blocks, 8 pairs). CTA (b0, p) computes planes {2p, 2p+1} for 32
// b-rows. Thread (ty = tid>>4, tx = tid&15) owns rows ty*2..+1, cols
// {tx, tx+16, tx+32, tx+48}. Same conflict-free layouts as R13.
extern "C" __global__ void __launch_bounds__(256)
zgp_kernel(const float* __restrict__ inputs) {
    __shared__ float4 xs[16 * JXS];
    __shared__ float4 ks[16 * JCS];
    const int tid = threadIdx.x;
    const int ty = tid >> 4, tx = tid & 15;
    const int b0 = blockIdx.x * 32;
    const int p = blockIdx.y;
    uint2* dst = (p < 4 ? g_zfA : g_zfB) + (size_t)(p & 3) * NBI;

    if (p == 7) {
        // planes 14,15: identically zero (contiguous uint4 fill)
#pragma unroll
        for (int r = 0; r < 2; r++) {
            int bi = (b0 + ty * 2 + r) * 64 + tx * 4;
            *(uint4*)&dst[bi]     = make_uint4(0, 0, 0, 0);
            *(uint4*)&dst[bi + 2] = make_uint4(0, 0, 0, 0);
        }
        return;
    }

    // load x0 tile (32 rows): xs[(j>>2)*JXS + r] = x0[b0+r][j..j+3]
#pragma unroll
    for (int l = 0; l < 2; l++) {
        int idx4 = l * 256 + tid;        // 0..511
        int el = idx4 * 4;
        int r = el >> 6, j = el & 63;    // r 0..31
        xs[(j >> 2) * JXS + r] = *(const float4*)(inputs + (size_t)(b0 + r) * TD + j);
    }
    __syncthreads();

    float accP[2][2][4];
#pragma unroll
    for (int pl = 0; pl < 2; pl++)
#pragma unroll
        for (int r = 0; r < 2; r++)
#pragma unroll
            for (int c = 0; c < 4; c++) accP[pl][r][c] = 0.f;

#pragma unroll
    for (int pl = 0; pl < 2; pl++) {
        const int kk = 2 * p + pl;
        if (kk == 0) {
#pragma unroll
            for (int r = 0; r < 2; r++)
#pragma unroll
                for (int c = 0; c < 4; c++) {
                    int j = tx + 16 * c;
                    accP[0][r][c] = ((const float*)&xs[(j >> 2) * JXS + ty * 2 + r])[j & 3];
                }
        } else if (kk <= 12) {
            const float* kp = g_Kp + (kk - 1) * 4096;
#pragma unroll
            for (int l = 0; l < 4; l++) {
                int idx4 = l * 256 + tid;
                int el = idx4 * 4;
                int r = el >> 6, j = el & 63;
                ks[(j >> 2) * JCS + r] = *(const float4*)(kp + el);
            }
            __syncthreads();
#pragma unroll 4
            for (int jc = 0; jc < 16; jc++) {
                float4 a4[2], b4[4];
#pragma unroll
                for (int r = 0; r < 2; r++) a4[r] = xs[jc * JXS + ty * 2 + r];
#pragma unroll
                for (int c = 0; c < 4; c++) b4[c] = ks[jc * JCS + tx + 16 * c];
#pragma unroll
                for (int r = 0; r < 2; r++)
#pragma unroll
                    for (int c = 0; c < 4; c++) {
                        float s = accP[pl][r][c];
                        s = fmaf(a4[r].x, b4[c].x, s);
                        s = fmaf(a4[r].y, b4[c].y, s);
                        s = fmaf(a4[r].z, b4[c].z, s);
                        s = fmaf(a4[r].w, b4[c].w, s);
                        accP[pl][r][c] = s;
                    }
            }
            __syncthreads();   // before next plane's ks load
        }
        // kk == 13: stays zero
    }

    const float ck0 = (2 * p     <= 12) ? c_coef[2 * p]     : 0.f;
    const float ck1 = (2 * p + 1 <= 12) ? c_coef[2 * p + 1] : 0.f;

    // store: element (b0+ty*2+r, tx+16c) -> dst[bi]; per-warp 2x128B runs per STG
#pragma unroll
    for (int r = 0; r < 2; r++) {
        int bir = (b0 + ty * 2 + r) * 64 + tx;
#pragma unroll
        for (int c = 0; c < 4; c++) {
            uint32_t h, l;
            split2h(accP[0][r][c] * ck0, accP[1][r][c] * ck1, h, l);
            dst[bir + 16 * c] = make_uint2(h, l);
        }
    }
}

// ---------------- eval: R13 staged + .cs STG.128 (measured ~44us, unchanged) ----
// grid (512, 2) x 256 thr. Warp W = blockIdx.x*8+wid owns b-row W (64 bi);
// blockIdx.y selects 8 of 16 t-fragment rows. 3-term fp16 split.
#define STRIDE 72
extern "C" __global__ void __launch_bounds__(256)
eval_kernel(float* __restrict__ out) {
    __shared__ float stg[8 * 16 * STRIDE];
    const int tid = threadIdx.x;
    const int wid = tid >> 5, lane = tid & 31;
    const int W = blockIdx.x * 8 + wid;          // b index
    const int mf0 = blockIdx.y * 8;
    float* ws = stg + wid * 16 * STRIDE;

    const int q = lane & 3;
    const int nl = lane >> 2;
    const size_t zbase = (size_t)q * NBI + W * 64 + nl;
    uint2 zA[8], zB[8];
#pragma unroll
    for (int nf = 0; nf < 8; nf++) {
        zA[nf] = g_zfA[zbase + nf * 8];
        zB[nf] = g_zfB[zbase + nf * 8];
    }

    const int r = lane >> 2;
    const int cb = (lane & 3) * 2;
    float* obase = out + (size_t)W * TD;

#pragma unroll 1
    for (int mi = 0; mi < 8; mi++) {
        const int mf = mf0 + mi;
        uint4 ah = g_tfH[mf * 32 + lane];
        uint4 al = g_tfL[mf * 32 + lane];

        float acc[8][4];
#pragma unroll
        for (int nf = 0; nf < 8; nf++)
#pragma unroll
            for (int q2 = 0; q2 < 4; q2++) acc[nf][q2] = 0.f;

#pragma unroll
        for (int nf = 0; nf < 8; nf++) {
            mma16816h(acc[nf], ah, zA[nf].x, zB[nf].x);   // hi * hi
            mma16816h(acc[nf], ah, zA[nf].y, zB[nf].y);   // hi * lo
            mma16816h(acc[nf], al, zA[nf].x, zB[nf].x);   // lo * hi
        }

        // stage tile [16 t][64 i]
#pragma unroll
        for (int nf = 0; nf < 8; nf++) {
            int col = nf * 8 + cb;
            *(float2*)&ws[r * STRIDE + col]       = make_float2(acc[nf][0], acc[nf][1]);
            *(float2*)&ws[(r + 8) * STRIDE + col] = make_float2(acc[nf][2], acc[nf][3]);
        }
        __syncwarp();

        // contiguous streaming stores: out[b][mf*16 .. +15][0..63] = 4KB contiguous
        float* op = obase + (size_t)mf * 1024;
#pragma unroll
        for (int p = 0; p < 8; p++) {
            int row = p * 2 + (lane >> 4);
            int col = (lane & 15) * 4;
            float4 vq = *(float4*)&ws[row * STRIDE + col];
            stg_cs4(op + row * 64 + col, vq);
        }
        __syncwarp();
    }
}

// ---------------- launch ----------------
extern "C" void kernel_launch(void* const* d_in, const int* in_sizes, int n_in,
                              void* d_out, int out_size) {
    const float* inputs = (const float*)d_in[0];
    const float* time   = (const float*)d_in[1];
    const float* kern   = (const float*)d_in[2];
    float* out = (float*)d_out;

    kpow_kernel<<<72, 64>>>(kern, time);
    zgp_kernel<<<dim3(128, 8), 256>>>(inputs);
    eval_kernel<<<dim3(512, 2), 256>>>(out);
}

// round 16
// speedup vs baseline: 1.5348x; 1.0376x over previous
#include <cuda_runtime.h>
#include <cuda_fp16.h>
#include <cstdint>

// Problem shape
#define B_DIM 4096
#define T_DIM 256
#define TD 16384             // T*D stride per batch row
#define NBI 262144           // B*64 flattened (b,i)
#define JCS 65               // zgp chunk stride in float4 (bank spread)

// K powers: g_Kp[(k-1)*4096 + i*64 + j] = (K^k)[i][j], k=1..12
__device__ float g_Kp[12 * 4096];
// Word-packed split fragments, plane-major within uint2:
//  g_zfA[q*NBI + bi] = (w(2q),   w(2q+1))    w(k) = hi16(k) | lo16(k)<<16
//  g_zfB[q*NBI + bi] = (w(2q+8), w(2q+9))
// eval PRMTs (w0,w1) -> (h0|h1<<16, l0|l1<<16) for the MMA operands.
__device__ uint2 g_zfA[4 * NBI];
__device__ uint2 g_zfB[4 * NBI];
// A fragments (t^k hi/lo): [mf*32 + lane]
__device__ uint4 g_tfH[16 * 32];
__device__ uint4 g_tfL[16 * 32];

__constant__ float c_coef[13] = {
    1.0f, 1.0f, 0.5f, 1.6666666666667e-1f, 4.1666666666667e-2f,
    8.3333333333333e-3f, 1.3888888888889e-3f, 1.9841269841270e-4f,
    2.4801587301587e-5f, 2.7557319223986e-6f, 2.7557319223986e-7f,
    2.5052108385442e-8f, 2.0876756987868e-9f};

// ---------------- helpers ----------------
__device__ __forceinline__ void split2h(float x, float y, uint32_t& H, uint32_t& L) {
    __half hx = __float2half_rn(x);
    __half hy = __float2half_rn(y);
    __half lx = __float2half_rn(x - __half2float(hx));
    __half ly = __float2half_rn(y - __half2float(hy));
    __half2 hh = __halves2half2(hx, hy);
    __half2 ll = __halves2half2(lx, ly);
    H = *(uint32_t*)&hh;
    L = *(uint32_t*)&ll;
}
// single-value word pack: hi16 | lo16<<16
__device__ __forceinline__ uint32_t packw(float v) {
    __half h = __float2half_rn(v);
    __half l = __float2half_rn(v - __half2float(h));
    return (uint32_t)__half_as_ushort(h) | ((uint32_t)__half_as_ushort(l) << 16);
}
__device__ __forceinline__ void mma16816h(float* c, const uint4& a, uint32_t b0, uint32_t b1) {
    asm volatile(
        "mma.sync.aligned.m16n8k16.row.col.f32.f16.f16.f32 "
        "{%0,%1,%2,%3}, {%4,%5,%6,%7}, {%8,%9}, {%0,%1,%2,%3};"
        : "+f"(c[0]), "+f"(c[1]), "+f"(c[2]), "+f"(c[3])
        : "r"(a.x), "r"(a.y), "r"(a.z), "r"(a.w), "r"(b0), "r"(b1));
}
__device__ __forceinline__ void stg_cs4(float* p, float4 v) {
    asm volatile("st.global.cs.v4.f32 [%0], {%1, %2, %3, %4};"
                 :: "l"(p), "f"(v.x), "f"(v.y), "f"(v.z), "f"(v.w) : "memory");
}

// ---------------- kpow (+ t-fragments) — R13-measured, unchanged ----------------
extern "C" __global__ void __launch_bounds__(64)
kpow_kernel(const float* __restrict__ Kmat, const float* __restrict__ time) {
    if (blockIdx.x >= 64) {
        int e = (blockIdx.x - 64) * 64 + threadIdx.x;   // 0..511 = mf*32 + lane
        int lane = e & 31;
        int mf = e >> 5;
        int r0 = mf * 16 + (lane >> 2);
        int r1 = r0 + 8;
        int k0 = (lane & 3) * 2;

        float t0 = time[r0], t1 = time[r1];
        float p0[16], p1[16];
        p0[0] = 1.f; p1[0] = 1.f;
#pragma unroll
        for (int k = 1; k < 13; k++) { p0[k] = p0[k - 1] * t0; p1[k] = p1[k - 1] * t1; }
#pragma unroll
        for (int k = 13; k < 16; k++) { p0[k] = 0.f; p1[k] = 0.f; }

        uint4 H, L;
        split2h(p0[k0], p0[k0 + 1], H.x, L.x);
        split2h(p1[k0], p1[k0 + 1], H.y, L.y);
        split2h(p0[k0 + 8], p0[k0 + 9], H.z, L.z);
        split2h(p1[k0 + 8], p1[k0 + 9], H.w, L.w);
        g_tfH[e] = H;
        g_tfL[e] = L;
        return;
    }

    __shared__ float vbuf[2][64];
    const int i = threadIdx.x;
    const int c = blockIdx.x;

    float kr[64];
    {
        const float4* kp = (const float4*)(Kmat + i * 64);
#pragma unroll
        for (int q = 0; q < 16; q++) {
            float4 v = kp[q];
            kr[q * 4 + 0] = v.x; kr[q * 4 + 1] = v.y;
            kr[q * 4 + 2] = v.z; kr[q * 4 + 3] = v.w;
        }
    }

    float v0 = Kmat[i * 64 + c];
    vbuf[0][i] = v0;
    g_Kp[i * 64 + c] = v0;
    __syncthreads();

    int cur = 0;
#pragma unroll
    for (int k = 2; k <= 12; k++) {
        const float4* vq = (const float4*)vbuf[cur];
        float s0 = 0.f, s1 = 0.f, s2 = 0.f, s3 = 0.f;
#pragma unroll
        for (int jq = 0; jq < 16; jq++) {
            float4 vv = vq[jq];
            s0 = fmaf(kr[jq * 4 + 0], vv.x, s0);
            s1 = fmaf(kr[jq * 4 + 1], vv.y, s1);
            s2 = fmaf(kr[jq * 4 + 2], vv.z, s2);
            s3 = fmaf(kr[jq * 4 + 3], vv.w, s3);
        }
        float s = (s0 + s1) + (s2 + s3);
        vbuf[cur ^ 1][i] = s;
        g_Kp[(k - 1) * 4096 + i * 64 + c] = s;
        cur ^= 1;
        __syncthreads();
    }
}

// ---------------- zgp: uniform single-plane CTAs ----------------
// grid (64, 13). gy = k in 1..12: ONE full 64x64x64 matmul for plane k,
// writes its 32-bit word (index k&1) of the target uint2.
// gy = 0: plane-0 copy (word 0 of g_zfA q0) + plane-13 zero (word 1 of
// g_zfB q2) + g_zfB q3 full zero.
extern "C" __global__ void __launch_bounds__(256)
zgp_kernel(const float* __restrict__ inputs) {
    __shared__ float4 xs[16 * JCS];
    __shared__ float4 ks[16 * JCS];
    const int tid = threadIdx.x;
    const int ty = tid >> 4, tx = tid & 15;
    const int b0 = blockIdx.x * 64;
    const int k = blockIdx.y;

    if (k == 0) {
        // plane 0 = x0 itself (word 0 of g_zfA q=0)
        uint32_t* d0 = (uint32_t*)g_zfA;
#pragma unroll
        for (int l = 0; l < 16; l++) {
            int idx = l * 256 + tid;       // = r*64 + j
            int r = idx >> 6, j = idx & 63;
            float v = inputs[(size_t)(b0 + r) * TD + j];
            d0[(size_t)2 * (b0 * 64 + idx)] = packw(v);
        }
        // plane 13 zero (word 1 of g_zfB q=2)
        uint32_t* d13 = (uint32_t*)(g_zfB + (size_t)2 * NBI) + 1;
#pragma unroll
        for (int l = 0; l < 16; l++) {
            int idx = l * 256 + tid;
            d13[(size_t)2 * (b0 * 64 + idx)] = 0u;
        }
        // planes 14,15 zero (g_zfB q=3 full)
        uint2* d3 = g_zfB + (size_t)3 * NBI + b0 * 64;
#pragma unroll
        for (int l = 0; l < 8; l++) {
            int idx = l * 256 + tid;       // uint4 index over 2048
            *(uint4*)&d3[idx * 2] = make_uint4(0, 0, 0, 0);
        }
        return;
    }

    // ---- plane k in 1..12: P_k = c_k * x0 @ (K^k)^T ----
    // load x0 tile: xs[(j>>2)*JCS + r] = x0[b0+r][j..j+3]
#pragma unroll
    for (int l = 0; l < 4; l++) {
        int idx4 = l * 256 + tid;
        int el = idx4 * 4;
        int r = el >> 6, j = el & 63;
        xs[(j >> 2) * JCS + r] = *(const float4*)(inputs + (size_t)(b0 + r) * TD + j);
    }
    // load K^k
    {
        const float* kp = g_Kp + (k - 1) * 4096;
#pragma unroll
        for (int l = 0; l < 4; l++) {
            int idx4 = l * 256 + tid;
            int el = idx4 * 4;
            int r = el >> 6, j = el & 63;
            ks[(j >> 2) * JCS + r] = *(const float4*)(kp + el);
        }
    }
    __syncthreads();

    float accP[4][4];
#pragma unroll
    for (int r = 0; r < 4; r++)
#pragma unroll
        for (int c = 0; c < 4; c++) accP[r][c] = 0.f;

#pragma unroll 4
    for (int jc = 0; jc < 16; jc++) {
        float4 a4[4], b4[4];
#pragma unroll
        for (int r = 0; r < 4; r++) a4[r] = xs[jc * JCS + ty * 4 + r];
#pragma unroll
        for (int c = 0; c < 4; c++) b4[c] = ks[jc * JCS + tx + 16 * c];
#pragma unroll
        for (int r = 0; r < 4; r++)
#pragma unroll
            for (int c = 0; c < 4; c++) {
                float s = accP[r][c];
                s = fmaf(a4[r].x, b4[c].x, s);
                s = fmaf(a4[r].y, b4[c].y, s);
                s = fmaf(a4[r].z, b4[c].z, s);
                s = fmaf(a4[r].w, b4[c].w, s);
                accP[r][c] = s;
            }
    }

    const float ck = c_coef[k];
    // target: word (k&1) of uint2 at (arr, q)
    uint2* base = (k < 8 ? g_zfA : g_zfB) + (size_t)((k & 7) >> 1) * NBI;
    uint32_t* dst32 = (uint32_t*)base + (k & 1);

#pragma unroll
    for (int r = 0; r < 4; r++) {
        size_t bir = (size_t)(b0 + ty * 4 + r) * 64 + tx;
#pragma unroll
        for (int c = 0; c < 4; c++)
            dst32[2 * (bir + 16 * c)] = packw(accP[r][c] * ck);
    }
}

// ---------------- eval: R13 staged + .cs STG.128; PRMT word->operand --------
// grid (512, 2) x 256 thr. Warp W = blockIdx.x*8+wid owns b-row W (64 bi);
// blockIdx.y selects 8 of 16 t-fragment rows. 3-term fp16 split.
#define STRIDE 72
extern "C" __global__ void __launch_bounds__(256)
eval_kernel(float* __restrict__ out) {
    __shared__ float stg[8 * 16 * STRIDE];
    const int tid = threadIdx.x;
    const int wid = tid >> 5, lane = tid & 31;
    const int W = blockIdx.x * 8 + wid;          // b index
    const int mf0 = blockIdx.y * 8;
    float* ws = stg + wid * 16 * STRIDE;

    const int q = lane & 3;
    const int nl = lane >> 2;
    const size_t zbase = (size_t)q * NBI + W * 64 + nl;
    uint2 zA[8], zB[8];
#pragma unroll
    for (int nf = 0; nf < 8; nf++) {
        uint2 a = g_zfA[zbase + nf * 8];
        uint2 b = g_zfB[zbase + nf * 8];
        // (w0, w1) -> (h0|h1<<16, l0|l1<<16)
        zA[nf] = make_uint2(__byte_perm(a.x, a.y, 0x5410), __byte_perm(a.x, a.y, 0x7632));
        zB[nf] = make_uint2(__byte_perm(b.x, b.y, 0x5410), __byte_perm(b.x, b.y, 0x7632));
    }

    const int r = lane >> 2;
    const int cb = (lane & 3) * 2;
    float* obase = out + (size_t)W * TD;

#pragma unroll 1
    for (int mi = 0; mi < 8; mi++) {
        const int mf = mf0 + mi;
        uint4 ah = g_tfH[mf * 32 + lane];
        uint4 al = g_tfL[mf * 32 + lane];

        float acc[8][4];
#pragma unroll
        for (int nf = 0; nf < 8; nf++)
#pragma unroll
            for (int q2 = 0; q2 < 4; q2++) acc[nf][q2] = 0.f;

#pragma unroll
        for (int nf = 0; nf < 8; nf++) {
            mma16816h(acc[nf], ah, zA[nf].x, zB[nf].x);   // hi * hi
            mma16816h(acc[nf], ah, zA[nf].y, zB[nf].y);   // hi * lo
            mma16816h(acc[nf], al, zA[nf].x, zB[nf].x);   // lo * hi
        }

        // stage tile [16 t][64 i]
#pragma unroll
        for (int nf = 0; nf < 8; nf++) {
            int col = nf * 8 + cb;
            *(float2*)&ws[r * STRIDE + col]       = make_float2(acc[nf][0], acc[nf][1]);
            *(float2*)&ws[(r + 8) * STRIDE + col] = make_float2(acc[nf][2], acc[nf][3]);
        }
        __syncwarp();

        // contiguous streaming stores: out[b][mf*16 .. +15][0..63] = 4KB contiguous
        float* op = obase + (size_t)mf * 1024;
#pragma unroll
        for (int p = 0; p < 8; p++) {
            int row = p * 2 + (lane >> 4);
            int col = (lane & 15) * 4;
            float4 vq = *(float4*)&ws[row * STRIDE + col];
            stg_cs4(op + row * 64 + col, vq);
        }
        __syncwarp();
    }
}

// ---------------- launch ----------------
extern "C" void kernel_launch(void* const* d_in, const int* in_sizes, int n_in,
                              void* d_out, int out_size) {
    const float* inputs = (const float*)d_in[0];
    const float* time   = (const float*)d_in[1];
    const float* kern   = (const float*)d_in[2];
    float* out = (float*)d_out;

    kpow_kernel<<<72, 64>>>(kern, time);
    zgp_kernel<<<dim3(64, 13), 256>>>(inputs);
    eval_kernel<<<dim3(512, 2), 256>>>(out);
}